// round 1
// baseline (speedup 1.0000x reference)
#include <cuda_runtime.h>

#define N_NODES 100000
#define N_EDGES 1000000
#define D_FEAT 64

// Scratch (allocation-free rule: __device__ globals)
__device__ float g_ex[N_EDGES];
__device__ float g_sum[N_NODES];

// ---------------------------------------------------------------------------
// Pass 0: zero the segment sums
// ---------------------------------------------------------------------------
__global__ void init_kernel() {
    int i = blockIdx.x * blockDim.x + threadIdx.x;
    if (i < N_NODES) g_sum[i] = 0.0f;
}

// ---------------------------------------------------------------------------
// Pass 1: per-edge dot product, e = exp(-0.01*|dot|), ex = exp(e),
//         atomicAdd into per-dst segment sum.
// 8 lanes cooperate per edge; stride-8 float4 loads so each LDG.128 across
// the 8-lane group covers one contiguous 128B line of the 256B row.
// ---------------------------------------------------------------------------
__global__ void edge_kernel(const float* __restrict__ feats,
                            const int* __restrict__ src,
                            const int* __restrict__ dst) {
    int tid = blockIdx.x * blockDim.x + threadIdx.x;
    int eid = tid >> 3;      // 8 lanes per edge
    int sub = tid & 7;
    if (eid >= N_EDGES) return;

    int s = src[eid];
    int d = dst[eid];

    const float4* fs = reinterpret_cast<const float4*>(feats + (size_t)s * D_FEAT);
    const float4* fd = reinterpret_cast<const float4*>(feats + (size_t)d * D_FEAT);

    // Row = 16 float4s. Lane `sub` takes elements sub and sub+8.
    float4 a0 = fs[sub];
    float4 a1 = fs[sub + 8];
    float4 b0 = fd[sub];
    float4 b1 = fd[sub + 8];

    float acc = a0.x * b0.x + a0.y * b0.y + a0.z * b0.z + a0.w * b0.w
              + a1.x * b1.x + a1.y * b1.y + a1.z * b1.z + a1.w * b1.w;

    // Reduce across the 8-lane group
    acc += __shfl_down_sync(0xFFFFFFFFu, acc, 4);
    acc += __shfl_down_sync(0xFFFFFFFFu, acc, 2);
    acc += __shfl_down_sync(0xFFFFFFFFu, acc, 1);

    if (sub == 0) {
        float e  = __expf(-0.01f * fabsf(acc));   // in (0.6, 1]
        // Softmax is shift-invariant; e is bounded in (0,1] so the reference's
        // segment-max subtraction is unnecessary for stability. Skip it.
        float ex = __expf(e);                     // in (1.9, 2.8)
        g_ex[eid] = ex;
        atomicAdd(&g_sum[d], ex);
    }
}

// ---------------------------------------------------------------------------
// Pass 2: out[e] = ex[e] / sum[dst[e]]
// ---------------------------------------------------------------------------
__global__ void div_kernel(const int* __restrict__ dst,
                           float* __restrict__ out) {
    int i = blockIdx.x * blockDim.x + threadIdx.x;
    if (i < N_EDGES) {
        out[i] = g_ex[i] / g_sum[dst[i]];
    }
}

// ---------------------------------------------------------------------------
extern "C" void kernel_launch(void* const* d_in, const int* in_sizes, int n_in,
                              void* d_out, int out_size) {
    const float* feats = (const float*)d_in[0];
    const int*   src   = (const int*)d_in[1];
    const int*   dst   = (const int*)d_in[2];
    float* out = (float*)d_out;

    init_kernel<<<(N_NODES + 255) / 256, 256>>>();
    edge_kernel<<<(N_EDGES * 8 + 255) / 256, 256>>>(feats, src, dst);
    div_kernel<<<(N_EDGES + 255) / 256, 256>>>(dst, out);
}